// round 7
// baseline (speedup 1.0000x reference)
#include <cuda_runtime.h>
#include <cuda_fp16.h>
#include <cuda_fp8.h>
#include <math.h>
#include <stdint.h>

#define BB 8
#define TT 512
#define VV 32128
#define DD 512
#define MM (BB*TT)          /* 4096 tokens */
#define NEG_INF (-1e9f)

// ---------------- scratch (device globals; no allocations allowed) ----------
__device__ uint8_t g_A8[(size_t)MM * VV];   // 131M e4m3  exp(l)
__device__ uint8_t g_B8[(size_t)DD * VV];   // 16 MB e4m3 (E^T * 64)
__device__ float  g_spred[MM * DD];
__device__ __half g_pnh[MM * DD];
__device__ __half g_rnh[MM * DD];
__device__ float  g_sim[BB * TT * TT];
__device__ float  g_pmax[MM];
__device__ float  g_rmax[MM];

#define NGEMM 128
#define NPROD 20
#define NGROUP 63            /* k-groups of 512 vocab columns (last = 384) */
__device__ int g_cnt[NGROUP];

// ---------------- PTX helpers (legacy-ISA: family-target safe) ----------------
__device__ __forceinline__ uint32_t smem_u32(const void* p) {
    uint32_t a;
    asm("{ .reg .u64 t; cvta.to.shared.u64 t, %1; cvt.u32.u64 %0, t; }" : "=r"(a) : "l"(p));
    return a;
}
__device__ __forceinline__ void cp16(uint32_t dst, const void* src) {
    asm volatile("cp.async.cg.shared.global [%0], [%1], 16;" :: "r"(dst), "l"(src));
}
__device__ __forceinline__ void ldm4(uint32_t* r, uint32_t addr) {
    asm volatile("ldmatrix.sync.aligned.m8n8.x4.shared.b16 {%0,%1,%2,%3}, [%4];"
                 : "=r"(r[0]), "=r"(r[1]), "=r"(r[2]), "=r"(r[3]) : "r"(addr));
}
__device__ __forceinline__ void mma_fp8(float* c, const uint32_t* a, uint32_t b0, uint32_t b1) {
    asm volatile(
        "mma.sync.aligned.m16n8k32.row.col.f32.e4m3.e4m3.f32 "
        "{%0,%1,%2,%3}, {%4,%5,%6,%7}, {%8,%9}, {%0,%1,%2,%3};"
        : "+f"(c[0]), "+f"(c[1]), "+f"(c[2]), "+f"(c[3])
        : "r"(a[0]), "r"(a[1]), "r"(a[2]), "r"(a[3]), "r"(b0), "r"(b1));
}
__device__ __forceinline__ void mma_f16(float* c, const uint32_t* a, uint32_t b0, uint32_t b1) {
    asm volatile(
        "mma.sync.aligned.m16n8k16.row.col.f32.f16.f16.f32 "
        "{%0,%1,%2,%3}, {%4,%5,%6,%7}, {%8,%9}, {%0,%1,%2,%3};"
        : "+f"(c[0]), "+f"(c[1]), "+f"(c[2]), "+f"(c[3])
        : "r"(a[0]), "r"(a[1]), "r"(a[2]), "r"(a[3]), "r"(b0), "r"(b1));
}
__device__ __forceinline__ void wait_group_ready(int g) {
    while (true) {
        int v;
        asm volatile("ld.global.acquire.gpu.b32 %0, [%1];" : "=r"(v) : "l"(&g_cnt[g]));
        if (v >= NPROD) break;
        __nanosleep(64);
    }
}

// ---------------- reductions ----------------
__device__ __forceinline__ float blockReduceSum(float v) {
    __shared__ float sh[32];
    int lane = threadIdx.x & 31, wid = threadIdx.x >> 5;
    #pragma unroll
    for (int o = 16; o; o >>= 1) v += __shfl_xor_sync(0xffffffffu, v, o);
    if (lane == 0) sh[wid] = v;
    __syncthreads();
    int nw = (blockDim.x + 31) >> 5;
    float r = (threadIdx.x < nw) ? sh[threadIdx.x] : 0.0f;
    if (wid == 0) {
        #pragma unroll
        for (int o = 16; o; o >>= 1) r += __shfl_xor_sync(0xffffffffu, r, o);
        if (lane == 0) sh[0] = r;
    }
    __syncthreads();
    float out = sh[0];
    __syncthreads();
    return out;
}

// ---------------- kernel: zero the producer flags (per launch) --------------
__global__ void k_zero() {
    if (threadIdx.x < NGROUP) g_cnt[threadIdx.x] = 0;
}

// ---------------- kernel 0b: transpose E*64 -> E^T e4m3 -----------------
__global__ void k_castB(const float* __restrict__ E) {
    __shared__ float tile[32][33];
    const int v0 = blockIdx.x * 32, d0 = blockIdx.y * 32;
    const int tx = threadIdx.x & 31, ty = threadIdx.x >> 5;   // 8 row-strides
    for (int r = ty; r < 32; r += 8)
        tile[r][tx] = E[(size_t)(v0 + r) * DD + d0 + tx];
    __syncthreads();
    for (int r = ty; r < 32; r += 8) {
        __nv_fp8_e4m3 q(tile[tx][r] * 64.0f);
        g_B8[(size_t)(d0 + r) * VV + v0 + tx] = *reinterpret_cast<uint8_t*>(&q);
    }
}

// ---------------- fused kernel: producers (exp->fp8) + GEMM consumers --------
// C[4096,512] = exp(L) @ (E*64)  (fp32 accum; scale & softmax Z cancel in
// normalize). 148 CTAs, 1/SM (147KB smem): CTAs [0,128) GEMM, [128,148) exp.
#define KC8 128
#define ROW_BYTES 144                      /* 128 fp8 + 16B pad */
#define TILE_BYTES (128 * ROW_BYTES)       /* 18432 */
#define STAGE_BYTES (2 * TILE_BYTES)       /* 36864 */
#define NSTAGE 4
#define GEMM_SMEM (NSTAGE * STAGE_BYTES)   /* 147456 */
#define K_ITERS (VV / KC8)                 /* 251 */

__global__ void __launch_bounds__(256) k_fused(const float* __restrict__ logits) {
    const int bid = blockIdx.x;
    const int tid = threadIdx.x;

    if (bid >= NGEMM) {
        // ---------------- producer role: exp(l) -> e4m3, k-group sweep -------
        const int pid = bid - NGEMM;                 // 0..19
        for (int g = 0; g < NGROUP; g++) {
            const int c0 = g * 512;
            // 4096 rows x 64 col-chunks of 8 (guard tail columns)
            for (int idx = pid * 256 + tid; idx < MM * 64; idx += NPROD * 256) {
                const int row = idx >> 6;
                const int col = c0 + ((idx & 63) << 3);
                if (col < VV) {
                    const float* lp = logits + (size_t)row * VV + col;
                    float4 v1 = *reinterpret_cast<const float4*>(lp);
                    float4 v2 = *reinterpret_cast<const float4*>(lp + 4);
                    float4 e1 = make_float4(__expf(v1.x), __expf(v1.y), __expf(v1.z), __expf(v1.w));
                    float4 e2 = make_float4(__expf(v2.x), __expf(v2.y), __expf(v2.z), __expf(v2.w));
                    __nv_fp8x4_e4m3 p1(e1), p2(e2);
                    uint2 o;
                    o.x = *reinterpret_cast<uint32_t*>(&p1);
                    o.y = *reinterpret_cast<uint32_t*>(&p2);
                    *reinterpret_cast<uint2*>(g_A8 + (size_t)row * VV + col) = o;
                }
            }
            __syncthreads();
            if (tid == 0) {
                __threadfence();
                atomicAdd(&g_cnt[g], 1);
            }
        }
        return;
    }

    // ---------------- GEMM consumer role ------------------------------------
    extern __shared__ char smem[];
    const uint32_t sbase = smem_u32(smem);
    const int wid = tid >> 5, lane = tid & 31;
    const int bm = (bid >> 2) * 128;
    const int bn = (bid & 3) * 128;
    const int wm = (wid & 1) * 64;
    const int wn = (wid >> 1) * 32;

    float c[4][4][4];
    #pragma unroll
    for (int i = 0; i < 4; i++)
        #pragma unroll
        for (int j = 0; j < 4; j++)
            #pragma unroll
            for (int q = 0; q < 4; q++) c[i][j][q] = 0.0f;

    const int msel = lane >> 3, rin = lane & 7;
    const uint32_t aoff = (uint32_t)((wm + ((msel & 1) << 3) + rin) * ROW_BYTES + ((msel >> 1) << 4));
    const uint32_t boff = (uint32_t)((wn + ((msel >> 1) << 3) + rin) * ROW_BYTES + ((msel & 1) << 4));

    auto stage_load = [&](int it) {
        const int s = it & (NSTAGE - 1);
        const int k0 = it * KC8;
        const uint32_t sb = sbase + s * STAGE_BYTES;
        #pragma unroll
        for (int i = 0; i < 4; i++) {
            int chunk = tid + (i << 8);            // 0..1023
            int row = chunk >> 3, col = chunk & 7;
            uint32_t doff = (uint32_t)(row * ROW_BYTES + col * 16);
            cp16(sb + doff,              g_A8 + (size_t)(bm + row) * VV + k0 + col * 16);
            cp16(sb + TILE_BYTES + doff, g_B8 + (size_t)(bn + row) * VV + k0 + col * 16);
        }
        asm volatile("cp.async.commit_group;");
    };

    wait_group_ready(0);          // chunks 0..3 are in group 0
    stage_load(0);
    stage_load(1);
    stage_load(2);

    uint32_t a[2][4][4], b[2][2][4];

    for (int it = 0; it < K_ITERS; it++) {
        const int s = it & (NSTAGE - 1);
        asm volatile("cp.async.wait_group 2;");
        __syncthreads();

        // issue next stage's loads immediately so they overlap this compute
        const int j = it + 3;
        if (j < K_ITERS) {
            if ((j & 3) == 0) wait_group_ready(j >> 2);
            stage_load(j);
        } else {
            asm volatile("cp.async.commit_group;");
        }

        const uint32_t Ab = sbase + s * STAGE_BYTES;
        const uint32_t Bb = Ab + TILE_BYTES;

        // prologue: fragments for ks=0
        #pragma unroll
        for (int mi = 0; mi < 4; mi++) ldm4(a[0][mi], Ab + aoff + mi * (16 * ROW_BYTES));
        #pragma unroll
        for (int jj = 0; jj < 2; jj++) ldm4(b[0][jj], Bb + boff + jj * (16 * ROW_BYTES));

        #pragma unroll
        for (int ks = 0; ks < 4; ks++) {    // each ks = k32 fp8
            const int cur = ks & 1, nxt = cur ^ 1;
            if (ks < 3) {
                #pragma unroll
                for (int mi = 0; mi < 4; mi++)
                    ldm4(a[nxt][mi], Ab + aoff + mi * (16 * ROW_BYTES) + (ks + 1) * 32);
                #pragma unroll
                for (int jj = 0; jj < 2; jj++)
                    ldm4(b[nxt][jj], Bb + boff + jj * (16 * ROW_BYTES) + (ks + 1) * 32);
            }
            #pragma unroll
            for (int mi = 0; mi < 4; mi++)
                #pragma unroll
                for (int nj = 0; nj < 4; nj++) {
                    const uint32_t* bp = &b[cur][nj >> 1][(nj & 1) * 2];
                    mma_fp8(c[mi][nj], a[cur][mi], bp[0], bp[1]);
                }
        }
    }

    const int g = lane >> 2, tg = lane & 3;
    #pragma unroll
    for (int mi = 0; mi < 4; mi++) {
        const int row = bm + wm + mi * 16 + g;
        #pragma unroll
        for (int nj = 0; nj < 4; nj++) {
            const int col = bn + wn + nj * 8 + tg * 2;
            *reinterpret_cast<float2*>(&g_spred[(size_t)row * DD + col]) =
                make_float2(c[mi][nj][0], c[mi][nj][1]);
            *reinterpret_cast<float2*>(&g_spred[(size_t)(row + 8) * DD + col]) =
                make_float2(c[mi][nj][2], c[mi][nj][3]);
        }
    }
}

// ---------------- kernel 3: L2-normalize -> fp16 -----------------------------
__global__ void k_normalize(const float* __restrict__ Emb, const int* __restrict__ labels) {
    const int t = blockIdx.x;
    const int tid = threadIdx.x;   // 128 threads, 4 floats each
    float4 v = reinterpret_cast<const float4*>(g_spred + (size_t)t * DD)[tid];
    float ss = v.x * v.x + v.y * v.y + v.z * v.z + v.w * v.w;
    ss = blockReduceSum(ss);
    float s = 1.0f / fmaxf(sqrtf(ss), 1e-12f);
    __half h[4] = { __float2half(v.x * s), __float2half(v.y * s),
                    __float2half(v.z * s), __float2half(v.w * s) };
    reinterpret_cast<uint2*>(g_pnh + (size_t)t * DD)[tid] = *reinterpret_cast<uint2*>(h);

    int lab = labels[t];
    if (lab == -100) lab = 0;
    float4 w = reinterpret_cast<const float4*>(Emb + (size_t)lab * DD)[tid];
    float ss2 = w.x * w.x + w.y * w.y + w.z * w.z + w.w * w.w;
    ss2 = blockReduceSum(ss2);
    float s2 = 1.0f / fmaxf(sqrtf(ss2), 1e-12f);
    __half h2[4] = { __float2half(w.x * s2), __float2half(w.y * s2),
                     __float2half(w.z * s2), __float2half(w.w * s2) };
    reinterpret_cast<uint2*>(g_rnh + (size_t)t * DD)[tid] = *reinterpret_cast<uint2*>(h2);
}

// ---------------- kernel 4: sim[b] = Pn @ Rn^T  (fp16 mma) -------------------
#define KC16 64
#define SIM_ITERS (DD / KC16)   /* 8 */

__global__ void __launch_bounds__(256) k_sim_mma() {
    extern __shared__ char smem[];
    const uint32_t sbase = smem_u32(smem);
    const int tid = threadIdx.x;
    const int wid = tid >> 5, lane = tid & 31;
    const int b = blockIdx.z;
    const int bm = blockIdx.y * 128;   // pred rows i
    const int bn = blockIdx.x * 128;   // ref rows j
    const int wm = (wid & 1) * 64;
    const int wn = (wid >> 1) * 32;
    const __half* P = g_pnh + (size_t)b * TT * DD;
    const __half* R = g_rnh + (size_t)b * TT * DD;

    float c[4][4][4];
    #pragma unroll
    for (int i = 0; i < 4; i++)
        #pragma unroll
        for (int j = 0; j < 4; j++)
            #pragma unroll
            for (int q = 0; q < 4; q++) c[i][j][q] = 0.0f;

    const int msel = lane >> 3, rin = lane & 7;
    const uint32_t aoff = (uint32_t)((wm + ((msel & 1) << 3) + rin) * ROW_BYTES + ((msel >> 1) << 4));
    const uint32_t boff = (uint32_t)((wn + ((msel >> 1) << 3) + rin) * ROW_BYTES + ((msel & 1) << 4));

    auto stage_load = [&](int it) {
        const int s = it & (NSTAGE - 1);
        const int k0 = it * KC16;
        const uint32_t sb = sbase + s * STAGE_BYTES;
        #pragma unroll
        for (int i = 0; i < 4; i++) {
            int chunk = tid + (i << 8);
            int row = chunk >> 3, col = chunk & 7;
            uint32_t doff = (uint32_t)(row * ROW_BYTES + col * 16);
            cp16(sb + doff,              P + (size_t)(bm + row) * DD + k0 + col * 8);
            cp16(sb + TILE_BYTES + doff, R + (size_t)(bn + row) * DD + k0 + col * 8);
        }
        asm volatile("cp.async.commit_group;");
    };

    stage_load(0);
    stage_load(1);
    stage_load(2);

    for (int it = 0; it < SIM_ITERS; it++) {
        const int s = it & (NSTAGE - 1);
        asm volatile("cp.async.wait_group 2;");
        __syncthreads();

        if (it + 3 < SIM_ITERS) stage_load(it + 3);
        else asm volatile("cp.async.commit_group;");

        const uint32_t Ab = sbase + s * STAGE_BYTES;
        const uint32_t Bb = Ab + TILE_BYTES;

        #pragma unroll
        for (int ks = 0; ks < 4; ks++) {
            uint32_t a[4][4], bfr[2][4];
            #pragma unroll
            for (int mi = 0; mi < 4; mi++)
                ldm4(a[mi], Ab + aoff + mi * (16 * ROW_BYTES) + ks * 32);
            #pragma unroll
            for (int jj = 0; jj < 2; jj++)
                ldm4(bfr[jj], Bb + boff + jj * (16 * ROW_BYTES) + ks * 32);
            #pragma unroll
            for (int mi = 0; mi < 4; mi++)
                #pragma unroll
                for (int nj = 0; nj < 4; nj++) {
                    const uint32_t* bp = &bfr[nj >> 1][(nj & 1) * 2];
                    mma_f16(c[mi][nj], a[mi], bp[0], bp[1]);
                }
        }
    }

    const int g = lane >> 2, tg = lane & 3;
    float* simb = g_sim + (size_t)b * TT * TT;
    #pragma unroll
    for (int mi = 0; mi < 4; mi++) {
        const int row = bm + wm + mi * 16 + g;
        #pragma unroll
        for (int nj = 0; nj < 4; nj++) {
            const int col = bn + wn + nj * 8 + tg * 2;
            *reinterpret_cast<float2*>(&simb[(size_t)row * TT + col]) =
                make_float2(c[mi][nj][0], c[mi][nj][1]);
            *reinterpret_cast<float2*>(&simb[(size_t)(row + 8) * TT + col]) =
                make_float2(c[mi][nj][2], c[mi][nj][3]);
        }
    }
}

// ---------------- kernel 5: masked row+col max, fused -------------------------
__global__ void k_maxes(const int* __restrict__ labels) {
    const int b = blockIdx.x;
    const int j = threadIdx.x;               // 512 threads
    __shared__ unsigned char validI[TT];
    validI[j] = (labels[b * TT + j] != -100) ? 1 : 0;
    __syncthreads();
    const float* simb = g_sim + (size_t)b * TT * TT;

    // col max (recall term): thread j sweeps rows
    float m = NEG_INF;
    for (int i = 0; i < TT; i++)
        if (validI[i]) m = fmaxf(m, simb[(size_t)i * TT + j]);
    g_rmax[b * TT + j] = m;

    // row max (precision term): warp per row, strided
    const int wid = j >> 5, lane = j & 31;
    for (int i = wid; i < TT; i += 16) {
        float rm = NEG_INF;
        for (int cidx = lane; cidx < TT; cidx += 32) {
            float v = validI[cidx] ? simb[(size_t)i * TT + cidx] : NEG_INF;
            rm = fmaxf(rm, v);
        }
        #pragma unroll
        for (int o = 16; o; o >>= 1) rm = fmaxf(rm, __shfl_xor_sync(0xffffffffu, rm, o));
        if (lane == 0) g_pmax[b * TT + i] = rm;
    }
}

// ---------------- kernel 6: final reduction ----------------
__global__ void k_final(const int* __restrict__ labels, float* __restrict__ out) {
    __shared__ float sp[256], sr[256], sc[256];
    const int tid = threadIdx.x;
    float total = 0.0f;
    for (int b = 0; b < BB; b++) {
        float psum = 0.0f, rsum = 0.0f, cnt = 0.0f;
        for (int idx = tid; idx < TT; idx += 256) {
            if (labels[b * TT + idx] != -100) {
                psum += g_pmax[b * TT + idx];
                rsum += g_rmax[b * TT + idx];
                cnt  += 1.0f;
            }
        }
        sp[tid] = psum; sr[tid] = rsum; sc[tid] = cnt;
        __syncthreads();
        for (int s = 128; s > 0; s >>= 1) {
            if (tid < s) {
                sp[tid] += sp[tid + s];
                sr[tid] += sr[tid + s];
                sc[tid] += sc[tid + s];
            }
            __syncthreads();
        }
        if (tid == 0) {
            float cntv = sc[0];
            float dc = fmaxf(cntv, 1.0f);
            float prec = sp[0] / dc;
            float rec  = sr[0] / dc;
            float den = prec + rec;
            float f1 = (den > 0.0f) ? (2.0f * prec * rec / fmaxf(den, 1e-8f)) : 0.0f;
            total += (cntv > 0.0f) ? (1.0f - f1) : 0.0f;
        }
        __syncthreads();
    }
    if (tid == 0) out[0] = total / (float)BB;
}

// ---------------- launch ----------------
extern "C" void kernel_launch(void* const* d_in, const int* in_sizes, int n_in,
                              void* d_out, int out_size) {
    const float* logits = (const float*)d_in[0];   // [8,512,32128] f32
    const int*   labels = (const int*)d_in[1];     // [8,512] i32
    const float* emb    = (const float*)d_in[2];   // [32128,512] f32
    float* out = (float*)d_out;

    cudaFuncSetAttribute(k_fused, cudaFuncAttributeMaxDynamicSharedMemorySize, GEMM_SMEM);
    cudaFuncSetAttribute(k_sim_mma, cudaFuncAttributeMaxDynamicSharedMemorySize, GEMM_SMEM);

    k_zero<<<1, 64>>>();
    k_castB<<<dim3(VV / 32, DD / 32), 256>>>(emb);
    k_fused<<<NGEMM + NPROD, 256, GEMM_SMEM>>>(logits);
    k_normalize<<<MM, 128>>>(emb, labels);
    k_sim_mma<<<dim3(TT / 128, TT / 128, BB), 256, GEMM_SMEM>>>();
    k_maxes<<<BB, TT>>>(labels);
    k_final<<<1, 256>>>(labels, out);
}

// round 8
// speedup vs baseline: 1.4602x; 1.4602x over previous
#include <cuda_runtime.h>
#include <cuda_fp16.h>
#include <cuda_fp8.h>
#include <math.h>
#include <stdint.h>

#define BB 8
#define TT 512
#define VV 32128
#define DD 512
#define MM (BB*TT)          /* 4096 tokens */
#define NEG_INF (-1e9f)

// ---------------- scratch (device globals; no allocations allowed) ----------
__device__ uint8_t g_A8[(size_t)MM * VV];   // 131M e4m3  exp(l)
__device__ uint8_t g_B8[(size_t)DD * VV];   // 16 MB e4m3 (E^T * 64)
__device__ float  g_spred[MM * DD];
__device__ __half g_pnh[MM * DD];
__device__ __half g_rnh[MM * DD];
__device__ float  g_sim[BB * TT * TT];
__device__ float  g_pmax[MM];
__device__ float  g_rmax[MM];

#define NCONS 128            /* GEMM CTAs; each also produces its 32 A-rows */
#define NGROUP 63            /* k-groups of 512 vocab columns (last = 384) */
#define NCHUNK (NGROUP * 4)  /* production quarter-chunks per CTA: 252 */
__device__ int g_cnt[NGROUP];

// ---------------- PTX helpers (legacy-ISA: family-target safe) ----------------
__device__ __forceinline__ uint32_t smem_u32(const void* p) {
    uint32_t a;
    asm("{ .reg .u64 t; cvta.to.shared.u64 t, %1; cvt.u32.u64 %0, t; }" : "=r"(a) : "l"(p));
    return a;
}
__device__ __forceinline__ void cp16(uint32_t dst, const void* src) {
    asm volatile("cp.async.cg.shared.global [%0], [%1], 16;" :: "r"(dst), "l"(src));
}
__device__ __forceinline__ void ldm4(uint32_t* r, uint32_t addr) {
    asm volatile("ldmatrix.sync.aligned.m8n8.x4.shared.b16 {%0,%1,%2,%3}, [%4];"
                 : "=r"(r[0]), "=r"(r[1]), "=r"(r[2]), "=r"(r[3]) : "r"(addr));
}
__device__ __forceinline__ void mma_fp8(float* c, const uint32_t* a, uint32_t b0, uint32_t b1) {
    asm volatile(
        "mma.sync.aligned.m16n8k32.row.col.f32.e4m3.e4m3.f32 "
        "{%0,%1,%2,%3}, {%4,%5,%6,%7}, {%8,%9}, {%0,%1,%2,%3};"
        : "+f"(c[0]), "+f"(c[1]), "+f"(c[2]), "+f"(c[3])
        : "r"(a[0]), "r"(a[1]), "r"(a[2]), "r"(a[3]), "r"(b0), "r"(b1));
}
__device__ __forceinline__ void mma_f16(float* c, const uint32_t* a, uint32_t b0, uint32_t b1) {
    asm volatile(
        "mma.sync.aligned.m16n8k16.row.col.f32.f16.f16.f32 "
        "{%0,%1,%2,%3}, {%4,%5,%6,%7}, {%8,%9}, {%0,%1,%2,%3};"
        : "+f"(c[0]), "+f"(c[1]), "+f"(c[2]), "+f"(c[3])
        : "r"(a[0]), "r"(a[1]), "r"(a[2]), "r"(a[3]), "r"(b0), "r"(b1));
}
__device__ __forceinline__ void wait_group_ready(int g) {
    while (true) {
        int v;
        asm volatile("ld.global.acquire.gpu.b32 %0, [%1];" : "=r"(v) : "l"(&g_cnt[g]));
        if (v >= NCONS) break;
        __nanosleep(64);
    }
}

// ---------------- reductions ----------------
__device__ __forceinline__ float blockReduceSum(float v) {
    __shared__ float sh[32];
    int lane = threadIdx.x & 31, wid = threadIdx.x >> 5;
    #pragma unroll
    for (int o = 16; o; o >>= 1) v += __shfl_xor_sync(0xffffffffu, v, o);
    if (lane == 0) sh[wid] = v;
    __syncthreads();
    int nw = (blockDim.x + 31) >> 5;
    float r = (threadIdx.x < nw) ? sh[threadIdx.x] : 0.0f;
    if (wid == 0) {
        #pragma unroll
        for (int o = 16; o; o >>= 1) r += __shfl_xor_sync(0xffffffffu, r, o);
        if (lane == 0) sh[0] = r;
    }
    __syncthreads();
    float out = sh[0];
    __syncthreads();
    return out;
}

// ---------------- kernel: zero the producer flags (per launch) --------------
__global__ void k_zero() {
    if (threadIdx.x < NGROUP) g_cnt[threadIdx.x] = 0;
}

// ---------------- kernel 0b: transpose E*64 -> E^T e4m3 -----------------
__global__ void k_castB(const float* __restrict__ E) {
    __shared__ float tile[32][33];
    const int v0 = blockIdx.x * 32, d0 = blockIdx.y * 32;
    const int tx = threadIdx.x & 31, ty = threadIdx.x >> 5;   // 8 row-strides
    for (int r = ty; r < 32; r += 8)
        tile[r][tx] = E[(size_t)(v0 + r) * DD + d0 + tx];
    __syncthreads();
    for (int r = ty; r < 32; r += 8) {
        __nv_fp8_e4m3 q(tile[tx][r] * 64.0f);
        g_B8[(size_t)(d0 + r) * VV + v0 + tx] = *reinterpret_cast<uint8_t*>(&q);
    }
}

// ---------------- fused GEMM + in-CTA exp production -------------------------
// C[4096,512] = exp(L) @ (E*64)  (fp32 accum; scale & softmax Z cancel in
// normalize). 128 CTAs, 1/SM. Each CTA produces fp8 A for its 32 rows,
// 8 chunks (2 k-groups) ahead of consumption, software-pipelined so the
// logits LDG -> exp/store distance is one full k-iteration.
#define KC8 128
#define ROW_BYTES 144                      /* 128 fp8 + 16B pad */
#define TILE_BYTES (128 * ROW_BYTES)       /* 18432 */
#define STAGE_BYTES (2 * TILE_BYTES)       /* 36864 */
#define NSTAGE 4
#define GEMM_SMEM (NSTAGE * STAGE_BYTES)   /* 147456 */
#define K_ITERS (VV / KC8)                 /* 251 */

// chunk q (0..251): group g=q>>2, 8 rows [bid*32 + (q&3)*8, +8), 512 cols.
__device__ __forceinline__ void prod_load(const float* __restrict__ logits,
                                          int bid, int tid, int q, float lv[2][8]) {
    if (q >= NCHUNK) return;
    const int g = q >> 2, r = q & 3;
    const int row0 = (bid << 5) + (r << 3);
    #pragma unroll
    for (int k = 0; k < 2; k++) {
        const int u = tid + (k << 8);
        const int row = row0 + (u >> 6);
        const int col = (g << 9) + ((u & 63) << 3);
        if (col < VV) {
            const float* lp = logits + (size_t)row * VV + col;
            float4 a = *reinterpret_cast<const float4*>(lp);
            float4 b = *reinterpret_cast<const float4*>(lp + 4);
            lv[k][0] = a.x; lv[k][1] = a.y; lv[k][2] = a.z; lv[k][3] = a.w;
            lv[k][4] = b.x; lv[k][5] = b.y; lv[k][6] = b.z; lv[k][7] = b.w;
        }
    }
}
__device__ __forceinline__ void prod_store(int bid, int tid, int q, float lv[2][8]) {
    if (q >= NCHUNK) return;
    const int g = q >> 2, r = q & 3;
    const int row0 = (bid << 5) + (r << 3);
    #pragma unroll
    for (int k = 0; k < 2; k++) {
        const int u = tid + (k << 8);
        const int row = row0 + (u >> 6);
        const int col = (g << 9) + ((u & 63) << 3);
        if (col < VV) {
            float4 e1 = make_float4(__expf(lv[k][0]), __expf(lv[k][1]),
                                    __expf(lv[k][2]), __expf(lv[k][3]));
            float4 e2 = make_float4(__expf(lv[k][4]), __expf(lv[k][5]),
                                    __expf(lv[k][6]), __expf(lv[k][7]));
            __nv_fp8x4_e4m3 p1(e1), p2(e2);
            uint2 o;
            o.x = *reinterpret_cast<uint32_t*>(&p1);
            o.y = *reinterpret_cast<uint32_t*>(&p2);
            *reinterpret_cast<uint2*>(g_A8 + (size_t)row * VV + col) = o;
        }
    }
    if ((q & 3) == 3) {           // group complete for this CTA
        __syncthreads();
        if (tid == 0) {
            __threadfence();
            atomicAdd(&g_cnt[g], 1);
        }
    }
}

__global__ void __launch_bounds__(256) k_fused(const float* __restrict__ logits) {
    extern __shared__ char smem[];
    const uint32_t sbase = smem_u32(smem);
    const int bid = blockIdx.x;
    const int tid = threadIdx.x;
    const int wid = tid >> 5, lane = tid & 31;
    const int bm = (bid >> 2) * 128;
    const int bn = (bid & 3) * 128;
    const int wm = (wid & 1) * 64;
    const int wn = (wid >> 1) * 32;

    // -------- production prologue: chunks 0..7 (groups 0,1), preload 8 ------
    {
        float pv[2][8];
        #pragma unroll
        for (int q = 0; q < 8; q++) {
            prod_load(logits, bid, tid, q, pv);
            prod_store(bid, tid, q, pv);
        }
    }
    float lv[2][8];
    prod_load(logits, bid, tid, 8, lv);

    float c[4][4][4];
    #pragma unroll
    for (int i = 0; i < 4; i++)
        #pragma unroll
        for (int j = 0; j < 4; j++)
            #pragma unroll
            for (int q = 0; q < 4; q++) c[i][j][q] = 0.0f;

    const int msel = lane >> 3, rin = lane & 7;
    const uint32_t aoff = (uint32_t)((wm + ((msel & 1) << 3) + rin) * ROW_BYTES + ((msel >> 1) << 4));
    const uint32_t boff = (uint32_t)((wn + ((msel >> 1) << 3) + rin) * ROW_BYTES + ((msel & 1) << 4));

    auto stage_load = [&](int it) {
        const int s = it & (NSTAGE - 1);
        const int k0 = it * KC8;
        const uint32_t sb = sbase + s * STAGE_BYTES;
        #pragma unroll
        for (int i = 0; i < 4; i++) {
            int chunk = tid + (i << 8);            // 0..1023
            int row = chunk >> 3, col = chunk & 7;
            uint32_t doff = (uint32_t)(row * ROW_BYTES + col * 16);
            cp16(sb + doff,              g_A8 + (size_t)(bm + row) * VV + k0 + col * 16);
            cp16(sb + TILE_BYTES + doff, g_B8 + (size_t)(bn + row) * VV + k0 + col * 16);
        }
        asm volatile("cp.async.commit_group;");
    };

    wait_group_ready(0);
    stage_load(0);
    stage_load(1);
    stage_load(2);

    uint32_t a[2][4][4], b[2][2][4];

    for (int it = 0; it < K_ITERS; it++) {
        const int s = it & (NSTAGE - 1);
        asm volatile("cp.async.wait_group 2;");
        __syncthreads();

        // issue next stage's loads immediately so they overlap this compute
        const int j = it + 3;
        if (j < K_ITERS) {
            if ((j & 3) == 0) wait_group_ready(j >> 2);
            stage_load(j);
        } else {
            asm volatile("cp.async.commit_group;");
        }

        // production: store chunk loaded last iter, then load the next one.
        prod_store(bid, tid, it + 8, lv);
        prod_load(logits, bid, tid, it + 9, lv);

        const uint32_t Ab = sbase + s * STAGE_BYTES;
        const uint32_t Bb = Ab + TILE_BYTES;

        // prologue: fragments for ks=0
        #pragma unroll
        for (int mi = 0; mi < 4; mi++) ldm4(a[0][mi], Ab + aoff + mi * (16 * ROW_BYTES));
        #pragma unroll
        for (int jj = 0; jj < 2; jj++) ldm4(b[0][jj], Bb + boff + jj * (16 * ROW_BYTES));

        #pragma unroll
        for (int ks = 0; ks < 4; ks++) {    // each ks = k32 fp8
            const int cur = ks & 1, nxt = cur ^ 1;
            if (ks < 3) {
                #pragma unroll
                for (int mi = 0; mi < 4; mi++)
                    ldm4(a[nxt][mi], Ab + aoff + mi * (16 * ROW_BYTES) + (ks + 1) * 32);
                #pragma unroll
                for (int jj = 0; jj < 2; jj++)
                    ldm4(b[nxt][jj], Bb + boff + jj * (16 * ROW_BYTES) + (ks + 1) * 32);
            }
            #pragma unroll
            for (int mi = 0; mi < 4; mi++)
                #pragma unroll
                for (int nj = 0; nj < 4; nj++) {
                    const uint32_t* bp = &b[cur][nj >> 1][(nj & 1) * 2];
                    mma_fp8(c[mi][nj], a[cur][mi], bp[0], bp[1]);
                }
        }
    }

    const int g = lane >> 2, tg = lane & 3;
    #pragma unroll
    for (int mi = 0; mi < 4; mi++) {
        const int row = bm + wm + mi * 16 + g;
        #pragma unroll
        for (int nj = 0; nj < 4; nj++) {
            const int col = bn + wn + nj * 8 + tg * 2;
            *reinterpret_cast<float2*>(&g_spred[(size_t)row * DD + col]) =
                make_float2(c[mi][nj][0], c[mi][nj][1]);
            *reinterpret_cast<float2*>(&g_spred[(size_t)(row + 8) * DD + col]) =
                make_float2(c[mi][nj][2], c[mi][nj][3]);
        }
    }
}

// ---------------- kernel 3: L2-normalize -> fp16 -----------------------------
__global__ void k_normalize(const float* __restrict__ Emb, const int* __restrict__ labels) {
    const int t = blockIdx.x;
    const int tid = threadIdx.x;   // 128 threads, 4 floats each
    float4 v = reinterpret_cast<const float4*>(g_spred + (size_t)t * DD)[tid];
    float ss = v.x * v.x + v.y * v.y + v.z * v.z + v.w * v.w;
    ss = blockReduceSum(ss);
    float s = 1.0f / fmaxf(sqrtf(ss), 1e-12f);
    __half h[4] = { __float2half(v.x * s), __float2half(v.y * s),
                    __float2half(v.z * s), __float2half(v.w * s) };
    reinterpret_cast<uint2*>(g_pnh + (size_t)t * DD)[tid] = *reinterpret_cast<uint2*>(h);

    int lab = labels[t];
    if (lab == -100) lab = 0;
    float4 w = reinterpret_cast<const float4*>(Emb + (size_t)lab * DD)[tid];
    float ss2 = w.x * w.x + w.y * w.y + w.z * w.z + w.w * w.w;
    ss2 = blockReduceSum(ss2);
    float s2 = 1.0f / fmaxf(sqrtf(ss2), 1e-12f);
    __half h2[4] = { __float2half(w.x * s2), __float2half(w.y * s2),
                     __float2half(w.z * s2), __float2half(w.w * s2) };
    reinterpret_cast<uint2*>(g_rnh + (size_t)t * DD)[tid] = *reinterpret_cast<uint2*>(h2);
}

// ---------------- kernel 4: sim[b] = Pn @ Rn^T  (fp16 mma) -------------------
#define KC16 64
#define SIM_ITERS (DD / KC16)   /* 8 */

__global__ void __launch_bounds__(256) k_sim_mma() {
    extern __shared__ char smem[];
    const uint32_t sbase = smem_u32(smem);
    const int tid = threadIdx.x;
    const int wid = tid >> 5, lane = tid & 31;
    const int b = blockIdx.z;
    const int bm = blockIdx.y * 128;   // pred rows i
    const int bn = blockIdx.x * 128;   // ref rows j
    const int wm = (wid & 1) * 64;
    const int wn = (wid >> 1) * 32;
    const __half* P = g_pnh + (size_t)b * TT * DD;
    const __half* R = g_rnh + (size_t)b * TT * DD;

    float c[4][4][4];
    #pragma unroll
    for (int i = 0; i < 4; i++)
        #pragma unroll
        for (int j = 0; j < 4; j++)
            #pragma unroll
            for (int q = 0; q < 4; q++) c[i][j][q] = 0.0f;

    const int msel = lane >> 3, rin = lane & 7;
    const uint32_t aoff = (uint32_t)((wm + ((msel & 1) << 3) + rin) * ROW_BYTES + ((msel >> 1) << 4));
    const uint32_t boff = (uint32_t)((wn + ((msel >> 1) << 3) + rin) * ROW_BYTES + ((msel & 1) << 4));

    auto stage_load = [&](int it) {
        const int s = it & (NSTAGE - 1);
        const int k0 = it * KC16;
        const uint32_t sb = sbase + s * STAGE_BYTES;
        #pragma unroll
        for (int i = 0; i < 4; i++) {
            int chunk = tid + (i << 8);
            int row = chunk >> 3, col = chunk & 7;
            uint32_t doff = (uint32_t)(row * ROW_BYTES + col * 16);
            cp16(sb + doff,              P + (size_t)(bm + row) * DD + k0 + col * 8);
            cp16(sb + TILE_BYTES + doff, R + (size_t)(bn + row) * DD + k0 + col * 8);
        }
        asm volatile("cp.async.commit_group;");
    };

    stage_load(0);
    stage_load(1);
    stage_load(2);

    for (int it = 0; it < SIM_ITERS; it++) {
        const int s = it & (NSTAGE - 1);
        asm volatile("cp.async.wait_group 2;");
        __syncthreads();

        if (it + 3 < SIM_ITERS) stage_load(it + 3);
        else asm volatile("cp.async.commit_group;");

        const uint32_t Ab = sbase + s * STAGE_BYTES;
        const uint32_t Bb = Ab + TILE_BYTES;

        #pragma unroll
        for (int ks = 0; ks < 4; ks++) {
            uint32_t a[4][4], bfr[2][4];
            #pragma unroll
            for (int mi = 0; mi < 4; mi++)
                ldm4(a[mi], Ab + aoff + mi * (16 * ROW_BYTES) + ks * 32);
            #pragma unroll
            for (int jj = 0; jj < 2; jj++)
                ldm4(bfr[jj], Bb + boff + jj * (16 * ROW_BYTES) + ks * 32);
            #pragma unroll
            for (int mi = 0; mi < 4; mi++)
                #pragma unroll
                for (int nj = 0; nj < 4; nj++) {
                    const uint32_t* bp = &bfr[nj >> 1][(nj & 1) * 2];
                    mma_f16(c[mi][nj], a[mi], bp[0], bp[1]);
                }
        }
    }

    const int g = lane >> 2, tg = lane & 3;
    float* simb = g_sim + (size_t)b * TT * TT;
    #pragma unroll
    for (int mi = 0; mi < 4; mi++) {
        const int row = bm + wm + mi * 16 + g;
        #pragma unroll
        for (int nj = 0; nj < 4; nj++) {
            const int col = bn + wn + nj * 8 + tg * 2;
            *reinterpret_cast<float2*>(&simb[(size_t)row * TT + col]) =
                make_float2(c[mi][nj][0], c[mi][nj][1]);
            *reinterpret_cast<float2*>(&simb[(size_t)(row + 8) * TT + col]) =
                make_float2(c[mi][nj][2], c[mi][nj][3]);
        }
    }
}

// ---------------- kernel 5: masked row+col max, fused -------------------------
__global__ void k_maxes(const int* __restrict__ labels) {
    const int b = blockIdx.x;
    const int j = threadIdx.x;               // 512 threads
    __shared__ unsigned char validI[TT];
    validI[j] = (labels[b * TT + j] != -100) ? 1 : 0;
    __syncthreads();
    const float* simb = g_sim + (size_t)b * TT * TT;

    // col max (recall term): thread j sweeps rows
    float m = NEG_INF;
    for (int i = 0; i < TT; i++)
        if (validI[i]) m = fmaxf(m, simb[(size_t)i * TT + j]);
    g_rmax[b * TT + j] = m;

    // row max (precision term): warp per row, strided
    const int wid = j >> 5, lane = j & 31;
    for (int i = wid; i < TT; i += 16) {
        float rm = NEG_INF;
        for (int cidx = lane; cidx < TT; cidx += 32) {
            float v = validI[cidx] ? simb[(size_t)i * TT + cidx] : NEG_INF;
            rm = fmaxf(rm, v);
        }
        #pragma unroll
        for (int o = 16; o; o >>= 1) rm = fmaxf(rm, __shfl_xor_sync(0xffffffffu, rm, o));
        if (lane == 0) g_pmax[b * TT + i] = rm;
    }
}

// ---------------- kernel 6: final reduction ----------------
__global__ void k_final(const int* __restrict__ labels, float* __restrict__ out) {
    __shared__ float sp[256], sr[256], sc[256];
    const int tid = threadIdx.x;
    float total = 0.0f;
    for (int b = 0; b < BB; b++) {
        float psum = 0.0f, rsum = 0.0f, cnt = 0.0f;
        for (int idx = tid; idx < TT; idx += 256) {
            if (labels[b * TT + idx] != -100) {
                psum += g_pmax[b * TT + idx];
                rsum += g_rmax[b * TT + idx];
                cnt  += 1.0f;
            }
        }
        sp[tid] = psum; sr[tid] = rsum; sc[tid] = cnt;
        __syncthreads();
        for (int s = 128; s > 0; s >>= 1) {
            if (tid < s) {
                sp[tid] += sp[tid + s];
                sr[tid] += sr[tid + s];
                sc[tid] += sc[tid + s];
            }
            __syncthreads();
        }
        if (tid == 0) {
            float cntv = sc[0];
            float dc = fmaxf(cntv, 1.0f);
            float prec = sp[0] / dc;
            float rec  = sr[0] / dc;
            float den = prec + rec;
            float f1 = (den > 0.0f) ? (2.0f * prec * rec / fmaxf(den, 1e-8f)) : 0.0f;
            total += (cntv > 0.0f) ? (1.0f - f1) : 0.0f;
        }
        __syncthreads();
    }
    if (tid == 0) out[0] = total / (float)BB;
}

// ---------------- launch ----------------
extern "C" void kernel_launch(void* const* d_in, const int* in_sizes, int n_in,
                              void* d_out, int out_size) {
    const float* logits = (const float*)d_in[0];   // [8,512,32128] f32
    const int*   labels = (const int*)d_in[1];     // [8,512] i32
    const float* emb    = (const float*)d_in[2];   // [32128,512] f32
    float* out = (float*)d_out;

    cudaFuncSetAttribute(k_fused, cudaFuncAttributeMaxDynamicSharedMemorySize, GEMM_SMEM);
    cudaFuncSetAttribute(k_sim_mma, cudaFuncAttributeMaxDynamicSharedMemorySize, GEMM_SMEM);

    k_zero<<<1, 64>>>();
    k_castB<<<dim3(VV / 32, DD / 32), 256>>>(emb);
    k_fused<<<NCONS, 256, GEMM_SMEM>>>(logits);
    k_normalize<<<MM, 128>>>(emb, labels);
    k_sim_mma<<<dim3(TT / 128, TT / 128, BB), 256, GEMM_SMEM>>>();
    k_maxes<<<BB, TT>>>(labels);
    k_final<<<1, 256>>>(labels, out);
}